// round 14
// baseline (speedup 1.0000x reference)
#include <cuda_runtime.h>
#include <math.h>

// ---------------- problem constants ----------------
#define NG    64
#define ATOMS 32
#define NN    2048
#define HID   128
#define FEAT  64
#define BINS  32
#define D0    106
#define D1    85
#define D2    64

typedef unsigned long long u64;

// ---------------- f32x2 packed-math helpers ----------------
__device__ __forceinline__ u64 fma2(u64 a, u64 b, u64 c) {
    u64 d;
    asm("fma.rn.f32x2 %0, %1, %2, %3;" : "=l"(d) : "l"(a), "l"(b), "l"(c));
    return d;
}
__device__ __forceinline__ float fsum2(u64 a) {
    unsigned lo, hi;
    asm("mov.b64 {%0, %1}, %2;" : "=r"(lo), "=r"(hi) : "l"(a));
    return __uint_as_float(lo) + __uint_as_float(hi);
}
__device__ __forceinline__ u64 pack2(float x) {
    u64 d;
    unsigned u = __float_as_uint(x);
    asm("mov.b64 %0, {%1, %1};" : "=l"(d) : "r"(u));
    return d;
}
// ---------------- cp.async helpers ----------------
__device__ __forceinline__ void cp16(unsigned dst, const void* src) {
    asm volatile("cp.async.cg.shared.global [%0], [%1], 16;" :: "r"(dst), "l"(src));
}
#define CP_COMMIT() asm volatile("cp.async.commit_group;")
#define CP_WAIT(n)  asm volatile("cp.async.wait_group %0;" :: "n"(n))

// =====================================================================
// 8-row x 128-ch GEMM tile from smem (f32x2). W stride 33 f4-chunks,
// X stride 33 f4-chunks. Writes Out rows (stride 132 f) + bias.
// =====================================================================
__device__ __forceinline__ void gemm8(
    const float* Wbuf, const float* Xs, unsigned ch,
    unsigned inRow0, unsigned outRow0, float bias, float* Out)
{
    u64 acc[8];
#pragma unroll
    for (int r = 0; r < 8; ++r) acc[r] = 0;
    const ulonglong2* W2 = (const ulonglong2*)Wbuf + ch * 33;
    const ulonglong2* X2 = (const ulonglong2*)Xs + inRow0 * 33;
#pragma unroll 2
    for (int kk = 0; kk < 32; ++kk) {
        ulonglong2 w = W2[kk];
#pragma unroll
        for (int r = 0; r < 8; ++r) {
            ulonglong2 x = X2[r * 33 + kk];
            acc[r] = fma2(w.x, x.x, acc[r]);
            acc[r] = fma2(w.y, x.y, acc[r]);
        }
    }
#pragma unroll
    for (int r = 0; r < 8; ++r)
        Out[(outRow0 + r) * 132 + ch] = fsum2(acc[r]) + bias;
}

// =====================================================================
// Fused kernel: one block = one (graph, half). Whole pipeline in smem.
// grid 128 = 64 graphs x 2 halves, block 512.
// =====================================================================
__global__ __launch_bounds__(512, 1) void k_fused(
    const float* __restrict__ h, const float* __restrict__ pos,
    const float* __restrict__ nt, const int* __restrict__ batch,
    const float* __restrict__ Wemb, const float* __restrict__ Wqkv,
    const float* __restrict__ bqkv, const float* __restrict__ Wb,
    const float* __restrict__ bb, const float* __restrict__ Wg,
    const float* __restrict__ bg, const float* __restrict__ Wt,
    const float* __restrict__ bt, const float* __restrict__ Wd0,
    const float* __restrict__ bd0, const float* __restrict__ Wd1,
    const float* __restrict__ bd1, const float* __restrict__ Wd2,
    const float* __restrict__ bd2, float* __restrict__ out)
{
    extern __shared__ float sm[];
    float* Xs = sm;             // 32*132 = 4224
    float* Qs = sm + 4224;      // 16*132 = 2112 (own q; later vals; later Y)
    float* Ks = sm + 6336;      // 32*132
    float* Vs = sm + 10560;     // 32*132
    float* Bs = sm + 14784;     // 16*108
    float* Cs = sm + 16512;     // 16*88
    float* WA = sm + 17920;     // 16896 f weight buffer A
    float* WB = sm + 34816;     // 16896 f weight buffer B
    __shared__ float Ls[16 * 33];
    __shared__ float ntS[64];
    __shared__ float embS[128];
    __shared__ float4 posS[32];
    __shared__ float WtS[32], biasS[16], gateS[16], partS[16];
    __shared__ float islS;

    unsigned t = threadIdx.x;
    unsigned ch = t & 127u, qq = t >> 7;
    int g = blockIdx.x >> 1, hf = blockIdx.x & 1;
    int col0 = g * ATOMS;            // first atom of graph
    int row0 = col0 + hf * 16;       // first own query row (global)
    unsigned sb = (unsigned)__cvta_generic_to_shared(sm);
    const unsigned offWA = 17920u * 4, offWB = 34816u * 4;

    // ---- group0: Wemb (128x16 f4) -> WA, stride 17 f4 ----
#pragma unroll
    for (int i = 0; i < 4; ++i) {
        unsigned idx = t + i * 512u;
        cp16(sb + offWA + ((idx >> 4) * 17 + (idx & 15u)) * 16,
             ((const float4*)Wemb) + idx);
    }
    CP_COMMIT();
    // ---- group1: Wq (128x32 f4) -> WB, stride 33 f4 ----
#pragma unroll
    for (int i = 0; i < 8; ++i) {
        unsigned idx = t + i * 512u;
        cp16(sb + offWB + ((idx >> 5) * 33 + (idx & 31u)) * 16,
             ((const float4*)Wqkv) + idx);
    }
    CP_COMMIT();

    // ---- misc loads + isl partials (overlap the copies) ----
    if (t < 16) ((float4*)ntS)[t] = ((const float4*)(nt + g * FEAT))[t];
    if (t >= 32 && t < 64) {
        int a = t - 32;
        posS[a] = make_float4(pos[(col0 + a) * 3], pos[(col0 + a) * 3 + 1],
                              pos[(col0 + a) * 3 + 2], 0.f);
    }
    if (t >= 64 && t < 96) WtS[t - 64] = Wt[t - 64];
    {
        int4 b4 = ((const int4*)batch)[t];     // 512 threads x int4 = 2048
        int cnt = (b4.x == g) + (b4.y == g) + (b4.z == g) + (b4.w == g);
        for (int o = 16; o; o >>= 1) cnt += __shfl_down_sync(~0u, cnt, o);
        if ((t & 31u) == 0) partS[t >> 5] = (float)cnt;
    }

    CP_WAIT(1); __syncthreads();               // Wemb ready

    // ---- emb[g] = nt[g] @ Wemb^T : threads 0..127 ----
    if (t < 128) {
        const float4* W4 = (const float4*)WA + t * 17;
        const float4* n4 = (const float4*)ntS;
        float acc = 0.f;
#pragma unroll
        for (int f = 0; f < 16; ++f) {
            float4 w = W4[f], x = n4[f];
            acc = fmaf(w.x, x.x, acc); acc = fmaf(w.y, x.y, acc);
            acc = fmaf(w.z, x.z, acc); acc = fmaf(w.w, x.w, acc);
        }
        embS[t] = acc;
    }
    if (t == 0) {
        float s = 0.f;
#pragma unroll
        for (int i = 0; i < 16; ++i) s += partS[i];
        islS = rsqrtf(s);
    }
    __syncthreads();                            // WA free, embS ready

    // ---- group2: Wk -> WA ----
#pragma unroll
    for (int i = 0; i < 8; ++i) {
        unsigned idx = t + i * 512u;
        cp16(sb + offWA + ((idx >> 5) * 33 + (idx & 31u)) * 16,
             ((const float4*)(Wqkv + HID * HID)) + idx);
    }
    CP_COMMIT();

    // ---- x = h * emb[g] for all 32 atoms (1024 f4, 2/thread) ----
#pragma unroll
    for (int i = 0; i < 2; ++i) {
        unsigned idx = t + i * 512u;
        unsigned n = idx >> 5, c4 = idx & 31u;
        float4 hv = ((const float4*)(h + (col0 + n) * HID))[c4];
        float4 ev = ((const float4*)embS)[c4];
        ((float4*)Xs)[n * 33 + c4] =
            make_float4(hv.x * ev.x, hv.y * ev.y, hv.z * ev.z, hv.w * ev.w);
    }
    CP_WAIT(1); __syncthreads();                // Wq ready, Xs ready

    // ---- bias & gate for own 16 rows: warp w -> row w ----
    {
        unsigned w = t >> 5, l = t & 31u;
        const float* xr = Xs + (hf * 16 + w) * 132;
        float pb = 0.f, pg = 0.f;
#pragma unroll
        for (int m = 0; m < 4; ++m) {
            float xv = xr[l + 32 * m];
            pb = fmaf(xv, Wb[l + 32 * m], pb);
            pg = fmaf(xv, Wg[l + 32 * m], pg);
        }
        for (int o = 16; o; o >>= 1) {
            pb += __shfl_down_sync(~0u, pb, o);
            pg += __shfl_down_sync(~0u, pg, o);
        }
        if (l == 0) {
            biasS[w] = pb + bb[0];
            float z = pg + bg[0];
            gateS[w] = 1.f / (1.f + __expf(-z));
        }
    }
    // ---- q gemm: own 16 rows only (qq<2 active) ----
    if (qq < 2)
        gemm8(WB, Xs, ch, hf * 16 + qq * 8, qq * 8, bqkv[ch], Qs);
    __syncthreads();                            // WB free

    // ---- group3: Wv -> WB ----
#pragma unroll
    for (int i = 0; i < 8; ++i) {
        unsigned idx = t + i * 512u;
        cp16(sb + offWB + ((idx >> 5) * 33 + (idx & 31u)) * 16,
             ((const float4*)(Wqkv + 2 * HID * HID)) + idx);
    }
    CP_COMMIT();
    CP_WAIT(1); __syncthreads();                // Wk ready

    // ---- k gemm: all 32 rows ----
    gemm8(WA, Xs, ch, qq * 8, qq * 8, bqkv[HID + ch], Ks);
    __syncthreads();                            // WA free

    // ---- group4: W0 (Wd0 106x32 f4) -> WA, stride 33 ----
#pragma unroll
    for (int i = 0; i < 7; ++i) {
        unsigned idx = t + i * 512u;
        if (idx < (unsigned)(D0 * 32))
            cp16(sb + offWA + ((idx >> 5) * 33 + (idx & 31u)) * 16,
                 ((const float4*)Wd0) + idx);
    }
    CP_COMMIT();
    CP_WAIT(1); __syncthreads();                // Wv ready

    // ---- v gemm: all 32 rows ----
    gemm8(WB, Xs, ch, qq * 8, qq * 8, bqkv[2 * HID + ch], Vs);
    __syncthreads();                            // WB free

    // ---- manual stage W1 (85x106 -> stride 108) and W2 (64x85 -> stride 92)
    //      into WB; LDG latency hidden under attention below ----
    for (unsigned idx = t; idx < (unsigned)(D1 * D0); idx += 512) {
        unsigned r = idx / D0, c = idx - r * D0;
        WB[r * 108 + c] = Wd1[idx];
    }
    for (unsigned idx = t; idx < (unsigned)(D2 * D1); idx += 512) {
        unsigned r = idx / D1, c = idx - r * D1;
        WB[9180 + r * 92 + c] = Wd2[idx];
    }
    for (unsigned i = t; i < 85u * 2u; i += 512) {
        unsigned r = i >> 1; WB[r * 108 + 106 + (i & 1u)] = 0.f;
    }
    for (unsigned i = t; i < 64u * 7u; i += 512) {
        unsigned r = i / 7u; WB[9180 + r * 92 + 85 + (i - r * 7u)] = 0.f;
    }

    // ---- attention logits: (i,j) one per thread ----
    {
        unsigned i = t >> 5, j = t & 31u;
        const ulonglong2* Q2 = (const ulonglong2*)Qs + i * 33;
        const ulonglong2* K2 = (const ulonglong2*)Ks + j * 33;
        u64 acc = 0;
#pragma unroll 8
        for (int kk = 0; kk < 32; ++kk) {
            ulonglong2 q2 = Q2[kk], k2 = K2[kk];
            acc = fma2(q2.x, k2.x, acc);
            acc = fma2(q2.y, k2.y, acc);
        }
        float qk = fsum2(acc);
        float4 pi = posS[hf * 16 + i];
        float4 pj = posS[j];
        float dx = pi.x - pj.x, dy = pi.y - pj.y, dz = pi.z - pj.z;
        float d = sqrtf(fmaxf(dx * dx + dy * dy + dz * dz, 1e-12f));
        const float step = 10.f / 31.f;
        int m0 = (int)(d * (31.f / 10.f)) - 4;
        m0 = max(0, min(BINS - 10, m0));
        float tv = bt[0];
#pragma unroll
        for (int m = 0; m < 10; ++m) {
            float c = step * (float)(m0 + m);
            float df = d - c;
            tv = fmaf(__expf(-10.f * df * df), WtS[m0 + m], tv);
        }
        Ls[i * 33 + j] = qk * islS + biasS[i] + tv;
    }
    __syncthreads();

    // ---- softmax: warp w -> row w ----
    {
        unsigned w = t >> 5, l = t & 31u;
        float v = Ls[w * 33 + l];
        float m = v;
        for (int o = 16; o; o >>= 1) m = fmaxf(m, __shfl_xor_sync(~0u, m, o));
        float e = __expf(v - m);
        float s = e;
        for (int o = 16; o; o >>= 1) s += __shfl_xor_sync(~0u, s, o);
        Ls[w * 33 + l] = e / s;
    }
    __syncthreads();                            // Qs reads (logits) done

    // ---- attn@v * gate + x -> vals (reuse Qs region, rows 0..15) ----
    {
        unsigned w = t >> 5, lane = t & 31u;
        u64 a01 = 0, a23 = 0;
        const ulonglong2* V2 = (const ulonglong2*)Vs;
#pragma unroll 8
        for (int j = 0; j < 32; ++j) {
            u64 aa = pack2(Ls[w * 33 + j]);
            ulonglong2 v2 = V2[j * 33 + lane];
            a01 = fma2(aa, v2.x, a01);
            a23 = fma2(aa, v2.y, a23);
        }
        u64 gg = pack2(gateS[w]);
        ulonglong2 x2 = ((const ulonglong2*)(Xs + (hf * 16 + w) * 132))[lane];
        ulonglong2 o2;
        o2.x = fma2(a01, gg, x2.x);
        o2.y = fma2(a23, gg, x2.y);
        ((ulonglong2*)(Qs + w * 132))[lane] = o2;
    }
    CP_WAIT(0); __syncthreads();                // W0 ready, vals ready, W1/W2 visible

    // ---- dense L0: 128 -> 106, SiLU ----
    if (ch < D0) {
        u64 a0 = 0, a1 = 0, a2 = 0, a3 = 0;
        const ulonglong2* W2p = (const ulonglong2*)WA + ch * 33;
        const ulonglong2* X2p = (const ulonglong2*)Qs + (qq * 4) * 33;
#pragma unroll 4
        for (int kk = 0; kk < 32; ++kk) {
            ulonglong2 w = W2p[kk];
            ulonglong2 xa = X2p[kk], xb = X2p[33 + kk], xc = X2p[66 + kk], xd = X2p[99 + kk];
            a0 = fma2(w.x, xa.x, a0); a0 = fma2(w.y, xa.y, a0);
            a1 = fma2(w.x, xb.x, a1); a1 = fma2(w.y, xb.y, a1);
            a2 = fma2(w.x, xc.x, a2); a2 = fma2(w.y, xc.y, a2);
            a3 = fma2(w.x, xd.x, a3); a3 = fma2(w.y, xd.y, a3);
        }
        float bias = bd0[ch];
        int nb = qq * 4;
        float z0 = fsum2(a0) + bias, z1 = fsum2(a1) + bias;
        float z2 = fsum2(a2) + bias, z3 = fsum2(a3) + bias;
        Bs[(nb + 0) * 108 + ch] = z0 / (1.f + __expf(-z0));
        Bs[(nb + 1) * 108 + ch] = z1 / (1.f + __expf(-z1));
        Bs[(nb + 2) * 108 + ch] = z2 / (1.f + __expf(-z2));
        Bs[(nb + 3) * 108 + ch] = z3 / (1.f + __expf(-z3));
    } else if (ch < 108) {
        int nb = qq * 4;
#pragma unroll
        for (int n = 0; n < 4; ++n) Bs[(nb + n) * 108 + ch] = 0.f;
    }
    __syncthreads();

    // ---- dense L1: 106(->108) -> 85, SiLU ----
    if (ch < D1) {
        u64 a0 = 0, a1 = 0, a2 = 0, a3 = 0;
        const ulonglong2* W2p = (const ulonglong2*)WB + ch * 27;
        const ulonglong2* X2p = (const ulonglong2*)Bs + (qq * 4) * 27;
#pragma unroll 3
        for (int kk = 0; kk < 27; ++kk) {
            ulonglong2 w = W2p[kk];
            ulonglong2 xa = X2p[kk], xb = X2p[27 + kk], xc = X2p[54 + kk], xd = X2p[81 + kk];
            a0 = fma2(w.x, xa.x, a0); a0 = fma2(w.y, xa.y, a0);
            a1 = fma2(w.x, xb.x, a1); a1 = fma2(w.y, xb.y, a1);
            a2 = fma2(w.x, xc.x, a2); a2 = fma2(w.y, xc.y, a2);
            a3 = fma2(w.x, xd.x, a3); a3 = fma2(w.y, xd.y, a3);
        }
        float bias = bd1[ch];
        int nb = qq * 4;
        float z0 = fsum2(a0) + bias, z1 = fsum2(a1) + bias;
        float z2 = fsum2(a2) + bias, z3 = fsum2(a3) + bias;
        Cs[(nb + 0) * 88 + ch] = z0 / (1.f + __expf(-z0));
        Cs[(nb + 1) * 88 + ch] = z1 / (1.f + __expf(-z1));
        Cs[(nb + 2) * 88 + ch] = z2 / (1.f + __expf(-z2));
        Cs[(nb + 3) * 88 + ch] = z3 / (1.f + __expf(-z3));
    } else if (ch < 88) {
        int nb = qq * 4;
#pragma unroll
        for (int n = 0; n < 4; ++n) Cs[(nb + n) * 88 + ch] = 0.f;
    }
    __syncthreads();

    // ---- dense L2: 85(->88) -> 64; Y reuses Qs region ----
    float* Y = Qs;
    if (ch < D2) {
        u64 a0 = 0, a1 = 0, a2 = 0, a3 = 0;
        const ulonglong2* W2p = (const ulonglong2*)(WB + 9180) + ch * 23;
        const ulonglong2* X2p = (const ulonglong2*)Cs + (qq * 4) * 22;
#pragma unroll 2
        for (int kk = 0; kk < 22; ++kk) {
            ulonglong2 w = W2p[kk];
            ulonglong2 xa = X2p[kk], xb = X2p[22 + kk], xc = X2p[44 + kk], xd = X2p[66 + kk];
            a0 = fma2(w.x, xa.x, a0); a0 = fma2(w.y, xa.y, a0);
            a1 = fma2(w.x, xb.x, a1); a1 = fma2(w.y, xb.y, a1);
            a2 = fma2(w.x, xc.x, a2); a2 = fma2(w.y, xc.y, a2);
            a3 = fma2(w.x, xd.x, a3); a3 = fma2(w.y, xd.y, a3);
        }
        float bias = bd2[ch];
        int nb = qq * 4;
        Y[(nb + 0) * 64 + ch] = fsum2(a0) + bias;
        Y[(nb + 1) * 64 + ch] = fsum2(a1) + bias;
        Y[(nb + 2) * 64 + ch] = fsum2(a2) + bias;
        Y[(nb + 3) * 64 + ch] = fsum2(a3) + bias;
    }
    __syncthreads();

    // ---- log_softmax over 64: warp w -> node w ----
    {
        unsigned w = t >> 5, l = t & 31u;
        float v0 = Y[w * 64 + l], v1 = Y[w * 64 + l + 32];
        float m = fmaxf(v0, v1);
        for (int o = 16; o; o >>= 1) m = fmaxf(m, __shfl_xor_sync(~0u, m, o));
        float s = __expf(v0 - m) + __expf(v1 - m);
        for (int o = 16; o; o >>= 1) s += __shfl_xor_sync(~0u, s, o);
        float ls = m + __logf(s);
        int node = row0 + w;
        out[node * 64 + l]      = v0 - ls;
        out[node * 64 + l + 32] = v1 - ls;
    }
}

// =====================================================================
extern "C" void kernel_launch(void* const* d_in, const int* in_sizes, int n_in,
                              void* d_out, int out_size)
{
    const float* h     = (const float*)d_in[0];
    const float* pos   = (const float*)d_in[1];
    const float* nt    = (const float*)d_in[2];
    const int*   batch = (const int*)  d_in[3];
    const float* Wemb  = (const float*)d_in[4];
    const float* Wqkv  = (const float*)d_in[5];
    const float* bqkv  = (const float*)d_in[6];
    const float* Wb    = (const float*)d_in[7];
    const float* bb    = (const float*)d_in[8];
    const float* Wg    = (const float*)d_in[9];
    const float* bg    = (const float*)d_in[10];
    const float* Wt    = (const float*)d_in[11];
    const float* bt    = (const float*)d_in[12];
    const float* Wd0   = (const float*)d_in[13];
    const float* bd0   = (const float*)d_in[14];
    const float* Wd1   = (const float*)d_in[15];
    const float* bd1   = (const float*)d_in[16];
    const float* Wd2   = (const float*)d_in[17];
    const float* bd2   = (const float*)d_in[18];
    float* out = (float*)d_out;

    const int smem = 51712 * 4;   // 206848 B dynamic
    cudaFuncSetAttribute(k_fused, cudaFuncAttributeMaxDynamicSharedMemorySize, smem);

    k_fused<<<NG * 2, 512, smem>>>(h, pos, nt, batch, Wemb, Wqkv, bqkv,
                                   Wb, bb, Wg, bg, Wt, bt,
                                   Wd0, bd0, Wd1, bd1, Wd2, bd2, out);
}